// round 8
// baseline (speedup 1.0000x reference)
#include <cuda_runtime.h>
#include <cstdint>

#define BATCH    16384
#define IN_DIM   512
#define NH       128
#define NO       256
#define NNODES   (NH + NO)         // 384
#define SRCW     (IN_DIM + NH)     // 640
#define TB       64                // batch rows per tile (float2 per lane)
#define NTHREADS 1024
#define NWARPS   32
#define MAXE     7936              // 63.5KB of constant memory

// Edge table in constant memory: warp-uniform index -> LDC/ULDC broadcast,
// separate HW port from LSU, ~30cyc latency (vs 234 LDG L2).
__constant__ int2 c_edges[MAXE];

// Staging + per-node info rebuilt by prep each launch (deterministic).
__device__ int2 g_edges[MAXE];
__device__ int4 g_infoA[NNODES];     // per schedule slot: e0,e1,e2,e3
__device__ int2 g_infoB[NNODES];     // per schedule slot: e4, node_id

__device__ __forceinline__ float tanha(float z) {
    float r;
    asm("tanh.approx.f32 %0, %1;" : "=f"(r) : "f"(z));
    return r;
}

// ================= Fused prep: histogram + scan + scatter + LPT (1 block) =========
__global__ void __launch_bounds__(1024)
prep_all(const int* __restrict__ rows_h, const int* __restrict__ cols_h,
         const int* __restrict__ acts_h, const float* __restrict__ wh,
         const int* __restrict__ rows_o, const int* __restrict__ cols_o,
         const int* __restrict__ acts_o, const float* __restrict__ wo,
         int Eh, int Eo)
{
    __shared__ int cnt[NNODES * 4];
    __shared__ int off[NNODES * 4 + 1];
    __shared__ int wsum[32];

    const int tid = threadIdx.x, lane = tid & 31, wid = tid >> 5;

    for (int i = tid; i < NNODES * 4; i += 1024) cnt[i] = 0;
    __syncthreads();

    for (int e = tid; e < Eh; e += 1024)
        atomicAdd(&cnt[rows_h[e] * 4 + acts_h[e] - 1], 1);
    for (int e = tid; e < Eo; e += 1024)
        atomicAdd(&cnt[(NH + rows_o[e]) * 4 + acts_o[e] - 1], 1);
    __syncthreads();

    if (lane == 0) {
        const int base = wid * 48;
        int run = 0;
        for (int i = 0; i < 48; ++i) { off[base + i] = run; run += cnt[base + i]; }
        wsum[wid] = run;
    }
    __syncthreads();
    if (wid == 0) {
        const int v = wsum[lane];
        int ex = v;
        #pragma unroll
        for (int d = 1; d < 32; d <<= 1) {
            const int t = __shfl_up_sync(0xffffffffu, ex, d);
            if (lane >= d) ex += t;
        }
        ex -= v;
        wsum[lane] = ex;
        if (lane == 31) off[NNODES * 4] = ex + v;
    }
    __syncthreads();
    for (int i = tid; i < NNODES * 4; i += 1024) off[i] += wsum[i / 48];
    __syncthreads();

    for (int n = wid; n < NNODES; n += 32) {
        const bool hid = n < NH;
        const int* cols = hid ? cols_h : cols_o;
        const int* acts = hid ? acts_h : acts_o;
        const float* wp = hid ? wh : wo;
        const int sub = hid ? 0 : Eh;
        const int s = off[n * 4] - sub;
        const int e = off[(n + 1) * 4] - sub;
        int d0 = off[n * 4], d1 = off[n * 4 + 1], d2 = off[n * 4 + 2], d3 = off[n * 4 + 3];
        for (int c = s; c < e; c += 32) {
            const int idx = c + lane;
            const bool v = idx < e;
            const int act = v ? acts[idx] : 0;
            const int col = v ? cols[idx] : 0;
            const float w = v ? wp[idx] : 0.f;
            // byte-addr word: q = col*256 | ((col&31)<<3); lane addr = q ^ (lane<<3)
            const int pk = col * 256 | ((col & 31) << 3);
            #pragma unroll
            for (int a = 1; a <= 4; ++a) {
                const unsigned mm = __ballot_sync(0xffffffffu, act == a);
                int& d = (a == 1) ? d0 : (a == 2) ? d1 : (a == 3) ? d2 : d3;
                if (act == a) {
                    const int r = __popc(mm & ((1u << lane) - 1));
                    const float ww = (a == 4) ? 0.5f * w : w;   // sigmoid pre-halved
                    g_edges[d + r] = make_int2(pk, __float_as_int(ww));
                }
                d += __popc(mm);
            }
        }
    }
    __syncthreads();

    if (tid < NNODES) {
        const int n = tid;
        const bool hid = n < NH;
        const int cn = off[(n + 1) * 4] - off[n * 4];
        const int lo = hid ? 0 : NH, hi2 = hid ? NH : NNODES;
        int rank = 0;
        for (int j = lo; j < hi2; ++j) {
            const int cj = off[(j + 1) * 4] - off[j * 4];
            rank += (cj > cn) || (cj == cn && j < n);
        }
        const int r = rank >> 5;
        int wl = rank & 31;
        if (r & 1) wl = 31 - wl;
        const int slot = (hid ? 0 : NH) + r * 32 + wl;
        g_infoA[slot] = make_int4(off[n * 4], off[n * 4 + 1], off[n * 4 + 2], off[n * 4 + 3]);
        g_infoB[slot] = make_int2(off[(n + 1) * 4], hid ? n : n - NH);
    }
}

// ================= Main kernel ====================================================
#define EDGE_LOOP(E0, E1, BODY)                                              \
    _Pragma("unroll 4")                                                      \
    for (int e = (E0); e < (E1); ++e) {                                      \
        const int2 ed = c_edges[e];                                          \
        const float2 s = *(const float2*)(srcb + (ed.x ^ lane8));            \
        const float w = __int_as_float(ed.y);                                \
        BODY                                                                 \
    }

__device__ __forceinline__ float2 node_accum(const char* __restrict__ srcb,
                                             int lane8, int4 A, int e4)
{
    const float bias = 0.5f * (float)(e4 - A.w);
    float a0 = bias, a1 = bias;
    EDGE_LOOP(A.x, A.y, { a0 = fmaf(w, s.x, a0); a1 = fmaf(w, s.y, a1); })
    EDGE_LOOP(A.y, A.z, { a0 += tanha(w * s.x); a1 += tanha(w * s.y); })
    EDGE_LOOP(A.z, A.w, { a0 += fmaxf(w * s.x, 0.f); a1 += fmaxf(w * s.y, 0.f); })
    EDGE_LOOP(A.w, e4,  { a0 = fmaf(0.5f, tanha(w * s.x), a0);
                          a1 = fmaf(0.5f, tanha(w * s.y), a1); })
    return make_float2(a0, a1);
}

__global__ void __launch_bounds__(NTHREADS, 1)
wann_main(const float* __restrict__ x, float* __restrict__ out)
{
    extern __shared__ char sm[];
    float*  src = (float*)sm;                        // [640 cols * 256B] fp32 swizzled
    float2* buf = (float2*)sm;                       // ALIASES src: [NO][33] after compute

    const int tid = threadIdx.x, wid = tid >> 5, lane = tid & 31;
    const int lane8 = lane << 3;
    const char* srcb = (const char*)sm;
    const int b0t = blockIdx.x * TB;

    // ---- stage x tile into swizzled transposed SMEM ----
    {
        const int sub = lane & 7, bq = lane >> 3;
        for (int it = wid; it < 256; it += NWARPS) {
            const int cchunk = it & 15;
            const int bchunk = it >> 4;
            const int b = bchunk * 4 + bq;
            const int c = cchunk * 32 + sub * 4;
            const float4 v = *(const float4*)(x + (size_t)(b0t + b) * IN_DIM + c);
            #pragma unroll
            for (int j = 0; j < 4; ++j) {
                const int cc = c + j;
                const int g = cc * 32 + ((b >> 1) ^ (cc & 31));
                const float val = (j == 0) ? v.x : (j == 1) ? v.y : (j == 2) ? v.z : v.w;
                src[2 * g + (b & 1)] = val;
            }
        }
    }
    __syncthreads();

    // ---- hidden phase: warp = node (LPT), branch-free act segments ----
    #pragma unroll 1
    for (int rr = 0; rr < NH / NWARPS; ++rr) {
        const int slot = rr * NWARPS + wid;
        const int4 A  = __ldg(&g_infoA[slot]);
        const int2 Bi = __ldg(&g_infoB[slot]);
        const float2 r = node_accum(srcb, lane8, A, Bi.x);
        const int hc = IN_DIM + Bi.y;
        const int qh = hc * 256 | ((hc & 31) << 3);
        *(float2*)((char*)sm + (qh ^ lane8)) = r;
    }
    __syncthreads();

    // ---- output phase: 8 nodes per warp into registers ----
    float2 res[NO / NWARPS];
    int    onode[NO / NWARPS];
    #pragma unroll
    for (int rr = 0; rr < NO / NWARPS; ++rr) {
        const int slot = NH + rr * NWARPS + wid;
        const int4 A  = __ldg(&g_infoA[slot]);
        const int2 Bi = __ldg(&g_infoB[slot]);
        onode[rr] = Bi.y;
        const float2 r = node_accum(srcb, lane8, A, Bi.x);
        res[rr] = make_float2(tanha(r.x), tanha(r.y));
    }

    // ---- write-out: one scatter into transpose buffer (aliases src), coalesced ----
    __syncthreads();
    #pragma unroll
    for (int rr = 0; rr < NO / NWARPS; ++rr)
        buf[onode[rr] * 33 + lane] = res[rr];
    __syncthreads();
    #pragma unroll
    for (int ch = 0; ch < NO / 32; ++ch) {
        #pragma unroll
        for (int r2 = 0; r2 < 2; ++r2) {
            const int rb = wid + r2 * 32;
            const float2 v = buf[(ch * 32 + lane) * 33 + (rb >> 1)];
            out[(size_t)(b0t + rb) * NO + ch * 32 + lane] = (rb & 1) ? v.y : v.x;
        }
    }
}

extern "C" void kernel_launch(void* const* d_in, const int* in_sizes, int n_in,
                              void* d_out, int out_size)
{
    const float* x      = (const float*)d_in[0];
    const float* wh     = (const float*)d_in[1];
    const float* wo     = (const float*)d_in[2];
    const int*   rows_h = (const int*)d_in[3];
    const int*   cols_h = (const int*)d_in[4];
    const int*   acts_h = (const int*)d_in[5];
    const int*   rows_o = (const int*)d_in[6];
    const int*   cols_o = (const int*)d_in[7];
    const int*   acts_o = (const int*)d_in[8];
    float* out = (float*)d_out;

    const int Eh = in_sizes[1];
    const int Eo = in_sizes[2];
    const int Etot = Eh + Eo;

    prep_all<<<1, 1024>>>(rows_h, cols_h, acts_h, wh,
                          rows_o, cols_o, acts_o, wo, Eh, Eo);

    // Copy reordered edges into the constant bank (DtoD, graph-capturable).
    void* edges_dev = nullptr;
    cudaGetSymbolAddress(&edges_dev, g_edges);
    cudaMemcpyToSymbolAsync(c_edges, edges_dev, (size_t)Etot * sizeof(int2), 0,
                            cudaMemcpyDeviceToDevice, 0);

    const size_t smem = (size_t)SRCW * TB * 4;       // 160KB fp32 src tile
    cudaFuncSetAttribute(wann_main, cudaFuncAttributeMaxDynamicSharedMemorySize,
                         (int)smem);
    wann_main<<<BATCH / TB, NTHREADS, smem>>>(x, out);
}

// round 9
// speedup vs baseline: 2.8217x; 2.8217x over previous
#include <cuda_runtime.h>
#include <cuda_fp16.h>
#include <cstdint>

#define BATCH    16384
#define IN_DIM   512
#define NH       128
#define NO       256
#define NNODES   (NH + NO)         // 384
#define SRCW     (IN_DIM + NH)     // 640
#define TB       128               // batch rows per tile (4 per lane, fp16)
#define NTHREADS 1024
#define NWARPS   32
#define MAXE     16384
#define SRC_BYTES (SRCW * 256)     // 163840
#define BUFSTRIDE 132              // floats per node row in transpose buffer

// src layout: col-major fp16, 256B per col. Element (col, b) at byte
//   col*256 + (((b>>2) ^ (col&31)) << 3) + (b&3)*2
// Lane l (batches 4l..4l+3) reads 8B at q ^ (l<<3), q = col<<8 | ((col&31)<<3).
//
// Edge record (4B): (float_bits(w) & 0xFFFFFC00) | col
//   -> w recovered by masking (13 mantissa bits), col in low 10 bits.
// Node info (int2): w0 = e0 | d1<<13 | d2<<21 ; w1 = d3 | d4<<8 | local<<16

__device__ int  g_edges[MAXE];
__device__ int2 g_info[NNODES];

__device__ __forceinline__ float tanha(float z) {
    float r;
    asm("tanh.approx.f32 %0, %1;" : "=f"(r) : "f"(z));
    return r;
}

// ================= Fused prep: histogram + scan + scatter + LPT (1 block) =========
__global__ void __launch_bounds__(1024)
prep_all(const int* __restrict__ rows_h, const int* __restrict__ cols_h,
         const int* __restrict__ acts_h, const float* __restrict__ wh,
         const int* __restrict__ rows_o, const int* __restrict__ cols_o,
         const int* __restrict__ acts_o, const float* __restrict__ wo,
         int Eh, int Eo)
{
    __shared__ int cnt[NNODES * 4];
    __shared__ int off[NNODES * 4 + 1];
    __shared__ int wsum[32];

    const int tid = threadIdx.x, lane = tid & 31, wid = tid >> 5;

    for (int i = tid; i < NNODES * 4; i += 1024) cnt[i] = 0;
    __syncthreads();

    for (int e = tid; e < Eh; e += 1024)
        atomicAdd(&cnt[rows_h[e] * 4 + acts_h[e] - 1], 1);
    for (int e = tid; e < Eo; e += 1024)
        atomicAdd(&cnt[(NH + rows_o[e]) * 4 + acts_o[e] - 1], 1);
    __syncthreads();

    if (lane == 0) {
        const int base = wid * 48;
        int run = 0;
        for (int i = 0; i < 48; ++i) { off[base + i] = run; run += cnt[base + i]; }
        wsum[wid] = run;
    }
    __syncthreads();
    if (wid == 0) {
        const int v = wsum[lane];
        int ex = v;
        #pragma unroll
        for (int d = 1; d < 32; d <<= 1) {
            const int t = __shfl_up_sync(0xffffffffu, ex, d);
            if (lane >= d) ex += t;
        }
        ex -= v;
        wsum[lane] = ex;
        if (lane == 31) off[NNODES * 4] = ex + v;
    }
    __syncthreads();
    for (int i = tid; i < NNODES * 4; i += 1024) off[i] += wsum[i / 48];
    __syncthreads();

    // stable scatter: warp per node, ballot compaction per act
    for (int n = wid; n < NNODES; n += 32) {
        const bool hid = n < NH;
        const int* cols = hid ? cols_h : cols_o;
        const int* acts = hid ? acts_h : acts_o;
        const float* wp = hid ? wh : wo;
        const int sub = hid ? 0 : Eh;
        const int s = off[n * 4] - sub;
        const int e = off[(n + 1) * 4] - sub;
        int d0 = off[n * 4], d1 = off[n * 4 + 1], d2 = off[n * 4 + 2], d3 = off[n * 4 + 3];
        for (int c = s; c < e; c += 32) {
            const int idx = c + lane;
            const bool v = idx < e;
            const int act = v ? acts[idx] : 0;
            const int col = v ? cols[idx] : 0;
            const float w = v ? wp[idx] : 0.f;
            #pragma unroll
            for (int a = 1; a <= 4; ++a) {
                const unsigned mm = __ballot_sync(0xffffffffu, act == a);
                int& d = (a == 1) ? d0 : (a == 2) ? d1 : (a == 3) ? d2 : d3;
                if (act == a) {
                    const int r = __popc(mm & ((1u << lane) - 1));
                    const float ww = (a == 4) ? 0.5f * w : w;   // sigmoid pre-halved
                    g_edges[d + r] = (__float_as_int(ww) & 0xFFFFFC00) | col;
                }
                d += __popc(mm);
            }
        }
    }
    __syncthreads();

    // LPT schedules: hidden global over 128; output per-64-node chunk. Packed info.
    if (tid < NNODES) {
        const int n = tid;
        const int e0 = off[n * 4], e1 = off[n * 4 + 1], e2 = off[n * 4 + 2];
        const int e3 = off[n * 4 + 3], e4 = off[(n + 1) * 4];
        const int cn = e4 - e0;
        int slot, local;
        if (n < NH) {
            int rank = 0;
            for (int j = 0; j < NH; ++j) {
                const int cj = off[(j + 1) * 4] - off[j * 4];
                rank += (cj > cn) || (cj == cn && j < n);
            }
            const int r = rank >> 5;
            int wl = rank & 31;
            if (r & 1) wl = 31 - wl;
            slot = r * 32 + wl;
            local = n;                            // hidden node id
        } else {
            const int m = n - NH;                 // 0..255
            const int chunk = m >> 6;
            int rank = 0;
            for (int j = 0; j < 64; ++j) {
                const int jn = NH + chunk * 64 + j;
                const int cj = off[(jn + 1) * 4] - off[jn * 4];
                rank += (cj > cn) || (cj == cn && jn < n);
            }
            const int r = rank >> 5;
            int wl = rank & 31;
            if (r & 1) wl = 31 - wl;
            slot = NH + chunk * 64 + r * 32 + wl;
            local = m & 63;                       // position within 64-node chunk
        }
        const int w0 = e0 | ((e1 - e0) << 13) | ((e2 - e1) << 21);
        const int w1 = (e3 - e2) | ((e4 - e3) << 8) | (local << 16);
        g_info[slot] = make_int2(w0, w1);
    }
}

// ================= Main kernel ====================================================
#define EDGE_LOOP(E0, E1, BODY)                                              \
    _Pragma("unroll 4")                                                      \
    for (int e = (E0); e < (E1); ++e) {                                      \
        const int ed = se[e];                                                \
        const float w = __int_as_float(ed & 0xFFFFFC00);                     \
        const int col = ed & 1023;                                           \
        const int q = (col << 8) | ((col & 31) << 3);                        \
        const uint2 u = *(const uint2*)(srcb + (q ^ lane8));                 \
        const float2 f0 = __half22float2(*(const __half2*)&u.x);             \
        const float2 f1 = __half22float2(*(const __half2*)&u.y);             \
        BODY                                                                 \
    }

__device__ __forceinline__ float4 node_accum(const char* __restrict__ srcb,
                                             const int* __restrict__ se,
                                             int lane8,
                                             int e0, int e1, int e2, int e3, int e4)
{
    const float bias = 0.5f * (float)(e4 - e3);
    float4 a = make_float4(bias, bias, bias, bias);
    EDGE_LOOP(e0, e1, {                        // identity
        a.x = fmaf(w, f0.x, a.x); a.y = fmaf(w, f0.y, a.y);
        a.z = fmaf(w, f1.x, a.z); a.w = fmaf(w, f1.y, a.w); })
    EDGE_LOOP(e1, e2, {                        // tanh
        a.x += tanha(w * f0.x); a.y += tanha(w * f0.y);
        a.z += tanha(w * f1.x); a.w += tanha(w * f1.y); })
    EDGE_LOOP(e2, e3, {                        // relu
        a.x += fmaxf(w * f0.x, 0.f); a.y += fmaxf(w * f0.y, 0.f);
        a.z += fmaxf(w * f1.x, 0.f); a.w += fmaxf(w * f1.y, 0.f); })
    EDGE_LOOP(e3, e4, {                        // sigmoid (w pre-halved, bias folded)
        a.x = fmaf(0.5f, tanha(w * f0.x), a.x); a.y = fmaf(0.5f, tanha(w * f0.y), a.y);
        a.z = fmaf(0.5f, tanha(w * f1.x), a.z); a.w = fmaf(0.5f, tanha(w * f1.y), a.w); })
    return a;
}

#define UNPACK_INFO(I)                                                       \
    const int e0 = (I).x & 8191;                                             \
    const int e1 = e0 + (((I).x >> 13) & 255);                               \
    const int e2 = e1 + (((I).x >> 21) & 255);                               \
    const int e3 = e2 + ((I).y & 255);                                       \
    const int e4 = e3 + (((I).y >> 8) & 255);                                \
    const int node = (I).y >> 16;

__global__ void __launch_bounds__(NTHREADS, 1)
wann_main(const float* __restrict__ x, float* __restrict__ out, int Etot)
{
    extern __shared__ char sm[];
    char* srcb   = sm;                                     // fp16 src tile, 160KB
    int*  se     = (int*)(sm + SRC_BYTES);                 // [Etot] packed edges
    const int seN = (Etot + 3) & ~3;                       // 16B-align next section
    int2* s_info = (int2*)(se + seN);                      // [NNODES]
    float* buf   = (float*)(s_info + NNODES);              // [64][BUFSTRIDE]

    const int tid = threadIdx.x, wid = tid >> 5, lane = tid & 31;
    const int lane8 = lane << 3;
    const int b0t = blockIdx.x * TB;

    // ---- stage edges + info into SMEM ----
    for (int i = tid; i < Etot; i += NTHREADS) se[i] = g_edges[i];
    if (tid < NNODES) s_info[tid] = g_info[tid];

    // ---- stage x tile: warp wid owns batch rows 4wid..4wid+3 ----
    {
        const size_t bb = (size_t)(b0t + wid * 4) * IN_DIM;
        #pragma unroll 4
        for (int k = 0; k < 16; ++k) {
            const int c = k * 32 + lane;
            const float v0 = x[bb + c];
            const float v1 = x[bb + IN_DIM + c];
            const float v2 = x[bb + 2 * IN_DIM + c];
            const float v3 = x[bb + 3 * IN_DIM + c];
            const __half2 ha = __floats2half2_rn(v0, v1);
            const __half2 hb = __floats2half2_rn(v2, v3);
            uint2 pv;
            pv.x = *(const unsigned*)&ha;
            pv.y = *(const unsigned*)&hb;
            *(uint2*)(srcb + c * 256 + ((wid ^ lane) << 3)) = pv;  // (c&31)==lane
        }
    }
    __syncthreads();

    // ---- hidden phase: 4 rounds, warp = node (global LPT) ----
    #pragma unroll 1
    for (int rr = 0; rr < NH / NWARPS; ++rr) {
        const int2 I = s_info[rr * NWARPS + wid];
        UNPACK_INFO(I)
        const float4 a = node_accum(srcb, se, lane8, e0, e1, e2, e3, e4);
        const __half2 ha = __floats2half2_rn(a.x, a.y);
        const __half2 hb = __floats2half2_rn(a.z, a.w);
        uint2 pv;
        pv.x = *(const unsigned*)&ha;
        pv.y = *(const unsigned*)&hb;
        const int hc = IN_DIM + node;
        const int qh = (hc << 8) | ((hc & 31) << 3);
        *(uint2*)(srcb + (qh ^ lane8)) = pv;
    }
    __syncthreads();

    // ---- output: 4 rounds of one 64-node chunk (LPT within chunk) ----
    #pragma unroll 1
    for (int r = 0; r < 4; ++r) {
        float4 rv[2]; int loc[2];
        #pragma unroll
        for (int h = 0; h < 2; ++h) {
            const int2 I = s_info[NH + r * 64 + h * 32 + wid];
            UNPACK_INFO(I)
            loc[h] = node;
            const float4 a = node_accum(srcb, se, lane8, e0, e1, e2, e3, e4);
            rv[h] = make_float4(tanha(a.x), tanha(a.y), tanha(a.z), tanha(a.w));
        }
        __syncthreads();                      // buf free (previous readout done)
        #pragma unroll
        for (int h = 0; h < 2; ++h)
            *(float4*)(buf + loc[h] * BUFSTRIDE + lane * 4) = rv[h];
        __syncthreads();
        #pragma unroll
        for (int j = 0; j < 4; ++j) {
            const int b = j * 32 + wid;       // batch row within tile
            #pragma unroll
            for (int ch = 0; ch < 2; ++ch) {
                const int cc = ch * 32 + lane;
                out[(size_t)(b0t + b) * NO + r * 64 + cc] = buf[cc * BUFSTRIDE + b];
            }
        }
    }
}

extern "C" void kernel_launch(void* const* d_in, const int* in_sizes, int n_in,
                              void* d_out, int out_size)
{
    const float* x      = (const float*)d_in[0];
    const float* wh     = (const float*)d_in[1];
    const float* wo     = (const float*)d_in[2];
    const int*   rows_h = (const int*)d_in[3];
    const int*   cols_h = (const int*)d_in[4];
    const int*   acts_h = (const int*)d_in[5];
    const int*   rows_o = (const int*)d_in[6];
    const int*   cols_o = (const int*)d_in[7];
    const int*   acts_o = (const int*)d_in[8];
    float* out = (float*)d_out;

    const int Eh = in_sizes[1];
    const int Eo = in_sizes[2];
    const int Etot = Eh + Eo;

    prep_all<<<1, 1024>>>(rows_h, cols_h, acts_h, wh,
                          rows_o, cols_o, acts_o, wo, Eh, Eo);

    const int seN = (Etot + 3) & ~3;
    const size_t smem = (size_t)SRC_BYTES            // fp16 src tile
                      + (size_t)seN * 4              // packed edges
                      + (size_t)NNODES * 8           // packed node info
                      + (size_t)64 * BUFSTRIDE * 4;  // transpose buffer
    cudaFuncSetAttribute(wann_main, cudaFuncAttributeMaxDynamicSharedMemorySize,
                         (int)smem);
    wann_main<<<BATCH / TB, NTHREADS, smem>>>(x, out, Etot);
}

// round 10
// speedup vs baseline: 3.0868x; 1.0940x over previous
#include <cuda_runtime.h>
#include <cuda_fp16.h>
#include <cstdint>

#define BATCH    16384
#define IN_DIM   512
#define NH       128
#define NO       256
#define NNODES   (NH + NO)         // 384
#define SRCW     (IN_DIM + NH)     // 640
#define TB       128               // batch rows per tile (4 per lane, fp16)
#define NTHREADS 1024
#define NWARPS   32
#define MAXE     16384
#define SRC_BYTES (SRCW * 256)     // 163840
#define BUFSTRIDE 132              // floats per node row in transpose buffer

// src: col-major fp16, 256B/col. (col,b) at byte col*256 + (((b>>2)^(col&31))<<3) + (b&3)*2.
// Lane l reads 8B (batches 4l..4l+3) at q ^ (l<<3), q = col*256 | ((col&31)<<3)  [precomputed].
// Edge record (8B): {q, w_fp32} (sigmoid w pre-halved).
// Node info (int2): w0 = e0 | d1<<13 | d2<<21 ; w1 = d3 | d4<<8 | local<<16

__device__ int2 g_edges[MAXE];
__device__ int2 g_info[NNODES];

__device__ __forceinline__ float tanha(float z) {
    float r;
    asm("tanh.approx.f32 %0, %1;" : "=f"(r) : "f"(z));
    return r;
}

// ================= Fused prep: histogram + scan + scatter + LPT (1 block) =========
__global__ void __launch_bounds__(1024)
prep_all(const int* __restrict__ rows_h, const int* __restrict__ cols_h,
         const int* __restrict__ acts_h, const float* __restrict__ wh,
         const int* __restrict__ rows_o, const int* __restrict__ cols_o,
         const int* __restrict__ acts_o, const float* __restrict__ wo,
         int Eh, int Eo)
{
    __shared__ int cnt[NNODES * 4];
    __shared__ int off[NNODES * 4 + 1];
    __shared__ int wsum[32];

    const int tid = threadIdx.x, lane = tid & 31, wid = tid >> 5;

    for (int i = tid; i < NNODES * 4; i += 1024) cnt[i] = 0;
    __syncthreads();

    for (int e = tid; e < Eh; e += 1024)
        atomicAdd(&cnt[rows_h[e] * 4 + acts_h[e] - 1], 1);
    for (int e = tid; e < Eo; e += 1024)
        atomicAdd(&cnt[(NH + rows_o[e]) * 4 + acts_o[e] - 1], 1);
    __syncthreads();

    if (lane == 0) {
        const int base = wid * 48;
        int run = 0;
        for (int i = 0; i < 48; ++i) { off[base + i] = run; run += cnt[base + i]; }
        wsum[wid] = run;
    }
    __syncthreads();
    if (wid == 0) {
        const int v = wsum[lane];
        int ex = v;
        #pragma unroll
        for (int d = 1; d < 32; d <<= 1) {
            const int t = __shfl_up_sync(0xffffffffu, ex, d);
            if (lane >= d) ex += t;
        }
        ex -= v;
        wsum[lane] = ex;
        if (lane == 31) off[NNODES * 4] = ex + v;
    }
    __syncthreads();
    for (int i = tid; i < NNODES * 4; i += 1024) off[i] += wsum[i / 48];
    __syncthreads();

    // stable scatter: warp per node, ballot compaction per act
    for (int n = wid; n < NNODES; n += 32) {
        const bool hid = n < NH;
        const int* cols = hid ? cols_h : cols_o;
        const int* acts = hid ? acts_h : acts_o;
        const float* wp = hid ? wh : wo;
        const int sub = hid ? 0 : Eh;
        const int s = off[n * 4] - sub;
        const int e = off[(n + 1) * 4] - sub;
        int d0 = off[n * 4], d1 = off[n * 4 + 1], d2 = off[n * 4 + 2], d3 = off[n * 4 + 3];
        for (int c = s; c < e; c += 32) {
            const int idx = c + lane;
            const bool v = idx < e;
            const int act = v ? acts[idx] : 0;
            const int col = v ? cols[idx] : 0;
            const float w = v ? wp[idx] : 0.f;
            const int pk = col * 256 | ((col & 31) << 3);     // precomputed addr word
            #pragma unroll
            for (int a = 1; a <= 4; ++a) {
                const unsigned mm = __ballot_sync(0xffffffffu, act == a);
                int& d = (a == 1) ? d0 : (a == 2) ? d1 : (a == 3) ? d2 : d3;
                if (act == a) {
                    const int r = __popc(mm & ((1u << lane) - 1));
                    const float ww = (a == 4) ? 0.5f * w : w;  // sigmoid pre-halved
                    g_edges[d + r] = make_int2(pk, __float_as_int(ww));
                }
                d += __popc(mm);
            }
        }
    }
    __syncthreads();

    // LPT serpentine schedules: hidden over 128, output over all 256. Packed info.
    if (tid < NNODES) {
        const int n = tid;
        const int e0 = off[n * 4], e1 = off[n * 4 + 1], e2 = off[n * 4 + 2];
        const int e3 = off[n * 4 + 3], e4 = off[(n + 1) * 4];
        const int cn = e4 - e0;
        int slot, local;
        if (n < NH) {
            int rank = 0;
            for (int j = 0; j < NH; ++j) {
                const int cj = off[(j + 1) * 4] - off[j * 4];
                rank += (cj > cn) || (cj == cn && j < n);
            }
            const int r = rank >> 5;
            int wl = rank & 31;
            if (r & 1) wl = 31 - wl;
            slot = r * 32 + wl;
            local = n;
        } else {
            int rank = 0;
            for (int j = NH; j < NNODES; ++j) {
                const int cj = off[(j + 1) * 4] - off[j * 4];
                rank += (cj > cn) || (cj == cn && j < n);
            }
            const int r = rank >> 5;
            int wl = rank & 31;
            if (r & 1) wl = 31 - wl;
            slot = NH + r * 32 + wl;
            local = n - NH;                       // 0..255
        }
        const int w0 = e0 | ((e1 - e0) << 13) | ((e2 - e1) << 21);
        const int w1 = (e3 - e2) | ((e4 - e3) << 8) | (local << 16);
        g_info[slot] = make_int2(w0, w1);
    }
}

// ================= Main kernel ====================================================
#define EDGE_LOOP(E0, E1, BODY)                                              \
    _Pragma("unroll 4")                                                      \
    for (int e = (E0); e < (E1); ++e) {                                      \
        const int2 ed = se[e];                                               \
        const uint2 u = *(const uint2*)(srcb + (ed.x ^ lane8));              \
        const float2 f0 = __half22float2(*(const __half2*)&u.x);             \
        const float2 f1 = __half22float2(*(const __half2*)&u.y);             \
        const float w = __int_as_float(ed.y);                                \
        BODY                                                                 \
    }

__device__ __forceinline__ float4 node_accum(const char* __restrict__ srcb,
                                             const int2* __restrict__ se,
                                             int lane8,
                                             int e0, int e1, int e2, int e3, int e4)
{
    const float bias = 0.5f * (float)(e4 - e3);
    float4 a = make_float4(bias, bias, bias, bias);
    EDGE_LOOP(e0, e1, {                        // identity
        a.x = fmaf(w, f0.x, a.x); a.y = fmaf(w, f0.y, a.y);
        a.z = fmaf(w, f1.x, a.z); a.w = fmaf(w, f1.y, a.w); })
    EDGE_LOOP(e1, e2, {                        // tanh
        a.x += tanha(w * f0.x); a.y += tanha(w * f0.y);
        a.z += tanha(w * f1.x); a.w += tanha(w * f1.y); })
    EDGE_LOOP(e2, e3, {                        // relu
        a.x += fmaxf(w * f0.x, 0.f); a.y += fmaxf(w * f0.y, 0.f);
        a.z += fmaxf(w * f1.x, 0.f); a.w += fmaxf(w * f1.y, 0.f); })
    EDGE_LOOP(e3, e4, {                        // sigmoid (w pre-halved, bias folded)
        a.x = fmaf(0.5f, tanha(w * f0.x), a.x); a.y = fmaf(0.5f, tanha(w * f0.y), a.y);
        a.z = fmaf(0.5f, tanha(w * f1.x), a.z); a.w = fmaf(0.5f, tanha(w * f1.y), a.w); })
    return a;
}

#define UNPACK_INFO(I)                                                       \
    const int e0 = (I).x & 8191;                                             \
    const int e1 = e0 + (((I).x >> 13) & 255);                               \
    const int e2 = e1 + (((I).x >> 21) & 255);                               \
    const int e3 = e2 + ((I).y & 255);                                       \
    const int e4 = e3 + (((I).y >> 8) & 255);                                \
    const int node = (I).y >> 16;

__global__ void __launch_bounds__(NTHREADS, 1)
wann_main(const float* __restrict__ x, float* __restrict__ out, int Etot)
{
    extern __shared__ char sm[];
    char* srcb   = sm;                                      // fp16 src tile, 160KB
    int2* se     = (int2*)(sm + SRC_BYTES);                 // [Etot] packed edges, 8B
    int2* s_info = (int2*)(sm + SRC_BYTES + ((Etot * 8 + 15) & ~15));
    float* buf   = (float*)sm;                              // ALIASES src: [NO][BUFSTRIDE]

    const int tid = threadIdx.x, wid = tid >> 5, lane = tid & 31;
    const int lane8 = lane << 3;
    const int b0t = blockIdx.x * TB;

    // ---- stage edges + info into SMEM ----
    for (int i = tid; i < Etot; i += NTHREADS) se[i] = g_edges[i];
    if (tid < NNODES) s_info[tid] = g_info[tid];

    // ---- stage x tile: warp wid owns batch rows 4wid..4wid+3 ----
    {
        const size_t bb = (size_t)(b0t + wid * 4) * IN_DIM;
        #pragma unroll 4
        for (int k = 0; k < 16; ++k) {
            const int c = k * 32 + lane;
            const float v0 = x[bb + c];
            const float v1 = x[bb + IN_DIM + c];
            const float v2 = x[bb + 2 * IN_DIM + c];
            const float v3 = x[bb + 3 * IN_DIM + c];
            const __half2 ha = __floats2half2_rn(v0, v1);
            const __half2 hb = __floats2half2_rn(v2, v3);
            uint2 pv;
            pv.x = *(const unsigned*)&ha;
            pv.y = *(const unsigned*)&hb;
            *(uint2*)(srcb + c * 256 + ((wid ^ lane) << 3)) = pv;  // (c&31)==lane
        }
    }
    __syncthreads();

    // ---- hidden phase: 4 rounds, warp = node (global LPT) ----
    #pragma unroll 1
    for (int rr = 0; rr < NH / NWARPS; ++rr) {
        const int2 I = s_info[rr * NWARPS + wid];
        UNPACK_INFO(I)
        const float4 a = node_accum(srcb, se, lane8, e0, e1, e2, e3, e4);
        const __half2 ha = __floats2half2_rn(a.x, a.y);
        const __half2 hb = __floats2half2_rn(a.z, a.w);
        uint2 pv;
        pv.x = *(const unsigned*)&ha;
        pv.y = *(const unsigned*)&hb;
        const int hc = IN_DIM + node;
        const int qh = (hc << 8) | ((hc & 31) << 3);
        *(uint2*)(srcb + (qh ^ lane8)) = pv;
    }
    __syncthreads();

    // ---- output phase: all 8 nodes per warp into registers (src must stay live) ----
    float4 res[NO / NWARPS];
    #pragma unroll
    for (int rr = 0; rr < NO / NWARPS; ++rr) {
        const int2 I = s_info[NH + rr * NWARPS + wid];
        UNPACK_INFO(I)
        (void)node;
        const float4 a = node_accum(srcb, se, lane8, e0, e1, e2, e3, e4);
        res[rr] = make_float4(tanha(a.x), tanha(a.y), tanha(a.z), tanha(a.w));
    }

    // ---- scatter into transpose buffer (aliases the now-dead src tile) ----
    __syncthreads();
    #pragma unroll
    for (int rr = 0; rr < NO / NWARPS; ++rr) {
        const int node = s_info[NH + rr * NWARPS + wid].y >> 16;
        *(float4*)(buf + node * BUFSTRIDE + lane * 4) = res[rr];
    }
    __syncthreads();

    // ---- coalesced write-out: warp wid handles batch rows 4wid..4wid+3 ----
    #pragma unroll
    for (int j = 0; j < 4; ++j) {
        const int b = wid * 4 + j;
        #pragma unroll
        for (int ch = 0; ch < NO / 32; ++ch) {
            const int cc = ch * 32 + lane;
            out[(size_t)(b0t + b) * NO + cc] = buf[cc * BUFSTRIDE + b];
        }
    }
}

extern "C" void kernel_launch(void* const* d_in, const int* in_sizes, int n_in,
                              void* d_out, int out_size)
{
    const float* x      = (const float*)d_in[0];
    const float* wh     = (const float*)d_in[1];
    const float* wo     = (const float*)d_in[2];
    const int*   rows_h = (const int*)d_in[3];
    const int*   cols_h = (const int*)d_in[4];
    const int*   acts_h = (const int*)d_in[5];
    const int*   rows_o = (const int*)d_in[6];
    const int*   cols_o = (const int*)d_in[7];
    const int*   acts_o = (const int*)d_in[8];
    float* out = (float*)d_out;

    const int Eh = in_sizes[1];
    const int Eo = in_sizes[2];
    const int Etot = Eh + Eo;

    prep_all<<<1, 1024>>>(rows_h, cols_h, acts_h, wh,
                          rows_o, cols_o, acts_o, wo, Eh, Eo);

    const size_t smem = (size_t)SRC_BYTES                   // fp16 src tile (buf aliases)
                      + (size_t)((Etot * 8 + 15) & ~15)     // packed 8B edges
                      + (size_t)NNODES * 8;                 // packed node info
    cudaFuncSetAttribute(wann_main, cudaFuncAttributeMaxDynamicSharedMemorySize,
                         (int)smem);
    wann_main<<<BATCH / TB, NTHREADS, smem>>>(x, out, Etot);
}

// round 11
// speedup vs baseline: 3.1860x; 1.0321x over previous
#include <cuda_runtime.h>
#include <cuda_fp16.h>
#include <cstdint>

#define BATCH    16384
#define IN_DIM   512
#define NH       128
#define NO       256
#define NNODES   (NH + NO)         // 384
#define SRCW     (IN_DIM + NH)     // 640
#define TB       128               // batch rows per tile (4 per lane, fp16)
#define NTHREADS 1024
#define NWARPS   32
#define MAXE     16384
#define SRC_BYTES (SRCW * 256)     // 163840
#define BUFSTRIDE 132              // floats per node row in transpose buffer

// src: col-major fp16, 256B/col. (col,b) at byte col*256 + (((b>>2)^(col&31))<<3) + (b&3)*2.
// Lane l reads 8B (batches 4l..4l+3) at q ^ (l<<3), q = col*256 | ((col&31)<<3) [precomputed].
// Edge record (8B): {q, wbits}. For identity/relu: wbits = fp32 w.
//                              For tanh/sigmoid: wbits = half2(w, w) (sigmoid pre-halved).
// Node info (int2): w0 = e0 | d1<<13 | d2<<21 ; w1 = d3 | d4<<8 | local<<16

__device__ int2 g_edges[MAXE];
__device__ int2 g_info[NNODES];

__device__ __forceinline__ float tanha(float z) {
    float r;
    asm("tanh.approx.f32 %0, %1;" : "=f"(r) : "f"(z));
    return r;
}
__device__ __forceinline__ unsigned tanh_h2(unsigned z) {
    unsigned r;
    asm("tanh.approx.f16x2 %0, %1;" : "=r"(r) : "r"(z));
    return r;
}
// Packed fp32x2 helpers (PTX-only instructions on sm_103a)
__device__ __forceinline__ unsigned long long pack2(float x, float y) {
    unsigned long long r;
    asm("mov.b64 %0, {%1, %2};" : "=l"(r) : "f"(x), "f"(y));
    return r;
}
__device__ __forceinline__ float2 unpack2(unsigned long long a) {
    float2 f;
    asm("mov.b64 {%0, %1}, %2;" : "=f"(f.x), "=f"(f.y) : "l"(a));
    return f;
}
__device__ __forceinline__ void fma2(unsigned long long& a, unsigned long long m,
                                     unsigned long long p) {
    asm("fma.rn.f32x2 %0, %1, %2, %0;" : "+l"(a) : "l"(m), "l"(p));
}
__device__ __forceinline__ void add2(unsigned long long& a, unsigned long long p) {
    asm("add.rn.f32x2 %0, %1, %0;" : "+l"(a) : "l"(p));
}
__device__ __forceinline__ __half2 b2h2(unsigned b) { __half2 h; *(unsigned*)&h = b; return h; }
__device__ __forceinline__ unsigned h22b(__half2 h) { return *(unsigned*)&h; }

// ================= Fused prep: histogram + scan + scatter + LPT (1 block) =========
__global__ void __launch_bounds__(1024)
prep_all(const int* __restrict__ rows_h, const int* __restrict__ cols_h,
         const int* __restrict__ acts_h, const float* __restrict__ wh,
         const int* __restrict__ rows_o, const int* __restrict__ cols_o,
         const int* __restrict__ acts_o, const float* __restrict__ wo,
         int Eh, int Eo)
{
    __shared__ int cnt[NNODES * 4];
    __shared__ int off[NNODES * 4 + 1];
    __shared__ int wsum[32];

    const int tid = threadIdx.x, lane = tid & 31, wid = tid >> 5;

    for (int i = tid; i < NNODES * 4; i += 1024) cnt[i] = 0;
    __syncthreads();

    for (int e = tid; e < Eh; e += 1024)
        atomicAdd(&cnt[rows_h[e] * 4 + acts_h[e] - 1], 1);
    for (int e = tid; e < Eo; e += 1024)
        atomicAdd(&cnt[(NH + rows_o[e]) * 4 + acts_o[e] - 1], 1);
    __syncthreads();

    if (lane == 0) {
        const int base = wid * 48;
        int run = 0;
        for (int i = 0; i < 48; ++i) { off[base + i] = run; run += cnt[base + i]; }
        wsum[wid] = run;
    }
    __syncthreads();
    if (wid == 0) {
        const int v = wsum[lane];
        int ex = v;
        #pragma unroll
        for (int d = 1; d < 32; d <<= 1) {
            const int t = __shfl_up_sync(0xffffffffu, ex, d);
            if (lane >= d) ex += t;
        }
        ex -= v;
        wsum[lane] = ex;
        if (lane == 31) off[NNODES * 4] = ex + v;
    }
    __syncthreads();
    for (int i = tid; i < NNODES * 4; i += 1024) off[i] += wsum[i / 48];
    __syncthreads();

    // stable scatter: warp per node, ballot compaction per act
    for (int n = wid; n < NNODES; n += 32) {
        const bool hid = n < NH;
        const int* cols = hid ? cols_h : cols_o;
        const int* acts = hid ? acts_h : acts_o;
        const float* wp = hid ? wh : wo;
        const int sub = hid ? 0 : Eh;
        const int s = off[n * 4] - sub;
        const int e = off[(n + 1) * 4] - sub;
        int d0 = off[n * 4], d1 = off[n * 4 + 1], d2 = off[n * 4 + 2], d3 = off[n * 4 + 3];
        for (int c = s; c < e; c += 32) {
            const int idx = c + lane;
            const bool v = idx < e;
            const int act = v ? acts[idx] : 0;
            const int col = v ? cols[idx] : 0;
            const float w = v ? wp[idx] : 0.f;
            const int pk = col * 256 | ((col & 31) << 3);     // precomputed addr word
            #pragma unroll
            for (int a = 1; a <= 4; ++a) {
                const unsigned mm = __ballot_sync(0xffffffffu, act == a);
                int& d = (a == 1) ? d0 : (a == 2) ? d1 : (a == 3) ? d2 : d3;
                if (act == a) {
                    const int r = __popc(mm & ((1u << lane) - 1));
                    int wbits;
                    if (a == 2 || a == 4) {                   // tanh / sigmoid: half2 w
                        const float ww = (a == 4) ? 0.5f * w : w;
                        const __half2 hh = __float2half2_rn(ww);
                        wbits = *(const int*)&hh;
                    } else {
                        wbits = __float_as_int(w);            // identity / relu: fp32 w
                    }
                    g_edges[d + r] = make_int2(pk, wbits);
                }
                d += __popc(mm);
            }
        }
    }
    __syncthreads();

    // LPT serpentine schedules: hidden over 128, output over all 256. Packed info.
    if (tid < NNODES) {
        const int n = tid;
        const int e0 = off[n * 4], e1 = off[n * 4 + 1], e2 = off[n * 4 + 2];
        const int e3 = off[n * 4 + 3], e4 = off[(n + 1) * 4];
        const int cn = e4 - e0;
        int slot, local;
        if (n < NH) {
            int rank = 0;
            for (int j = 0; j < NH; ++j) {
                const int cj = off[(j + 1) * 4] - off[j * 4];
                rank += (cj > cn) || (cj == cn && j < n);
            }
            const int r = rank >> 5;
            int wl = rank & 31;
            if (r & 1) wl = 31 - wl;
            slot = r * 32 + wl;
            local = n;
        } else {
            int rank = 0;
            for (int j = NH; j < NNODES; ++j) {
                const int cj = off[(j + 1) * 4] - off[j * 4];
                rank += (cj > cn) || (cj == cn && j < n);
            }
            const int r = rank >> 5;
            int wl = rank & 31;
            if (r & 1) wl = 31 - wl;
            slot = NH + r * 32 + wl;
            local = n - NH;
        }
        const int w0 = e0 | ((e1 - e0) << 13) | ((e2 - e1) << 21);
        const int w1 = (e3 - e2) | ((e4 - e3) << 8) | (local << 16);
        g_info[slot] = make_int2(w0, w1);
    }
}

// ================= Main kernel ====================================================
__device__ __forceinline__ float4 node_accum(const char* __restrict__ srcb,
                                             const int2* __restrict__ se,
                                             int lane8,
                                             int e0, int e1, int e2, int e3, int e4)
{
    const float bias = 0.5f * (float)(e4 - e3);
    unsigned long long A01 = pack2(bias, bias);
    unsigned long long A23 = pack2(bias, bias);

    // identity: fp32 w, packed FFMA2
    #pragma unroll 4
    for (int e = e0; e < e1; ++e) {
        const int2 ed = se[e];
        const uint2 u = *(const uint2*)(srcb + (ed.x ^ lane8));
        const float w = __int_as_float(ed.y);
        const unsigned long long w2 = pack2(w, w);
        const float2 f0 = __half22float2(b2h2(u.x));
        const float2 f1 = __half22float2(b2h2(u.y));
        fma2(A01, w2, pack2(f0.x, f0.y));
        fma2(A23, w2, pack2(f1.x, f1.y));
    }
    // tanh: half2 w, HMUL2 + tanh.approx.f16x2
    #pragma unroll 4
    for (int e = e1; e < e2; ++e) {
        const int2 ed = se[e];
        const uint2 u = *(const uint2*)(srcb + (ed.x ^ lane8));
        const __half2 wh = b2h2((unsigned)ed.y);
        const float2 f0 = __half22float2(b2h2(tanh_h2(h22b(__hmul2(wh, b2h2(u.x))))));
        const float2 f1 = __half22float2(b2h2(tanh_h2(h22b(__hmul2(wh, b2h2(u.y))))));
        add2(A01, pack2(f0.x, f0.y));
        add2(A23, pack2(f1.x, f1.y));
    }
    // relu: fp32 w (exact), scalar mul+max then packed add
    #pragma unroll 4
    for (int e = e2; e < e3; ++e) {
        const int2 ed = se[e];
        const uint2 u = *(const uint2*)(srcb + (ed.x ^ lane8));
        const float w = __int_as_float(ed.y);
        const float2 f0 = __half22float2(b2h2(u.x));
        const float2 f1 = __half22float2(b2h2(u.y));
        add2(A01, pack2(fmaxf(w * f0.x, 0.f), fmaxf(w * f0.y, 0.f)));
        add2(A23, pack2(fmaxf(w * f1.x, 0.f), fmaxf(w * f1.y, 0.f)));
    }
    // sigmoid: half2 w pre-halved; 0.5*tanh + (bias already folded)
    {
        const unsigned long long C05 = pack2(0.5f, 0.5f);
        #pragma unroll 4
        for (int e = e3; e < e4; ++e) {
            const int2 ed = se[e];
            const uint2 u = *(const uint2*)(srcb + (ed.x ^ lane8));
            const __half2 wh = b2h2((unsigned)ed.y);
            const float2 f0 = __half22float2(b2h2(tanh_h2(h22b(__hmul2(wh, b2h2(u.x))))));
            const float2 f1 = __half22float2(b2h2(tanh_h2(h22b(__hmul2(wh, b2h2(u.y))))));
            fma2(A01, C05, pack2(f0.x, f0.y));
            fma2(A23, C05, pack2(f1.x, f1.y));
        }
    }
    const float2 r01 = unpack2(A01);
    const float2 r23 = unpack2(A23);
    return make_float4(r01.x, r01.y, r23.x, r23.y);
}

#define UNPACK_INFO(I)                                                       \
    const int e0 = (I).x & 8191;                                             \
    const int e1 = e0 + (((I).x >> 13) & 255);                               \
    const int e2 = e1 + (((I).x >> 21) & 255);                               \
    const int e3 = e2 + ((I).y & 255);                                       \
    const int e4 = e3 + (((I).y >> 8) & 255);                                \
    const int node = (I).y >> 16;

__global__ void __launch_bounds__(NTHREADS, 1)
wann_main(const float* __restrict__ x, float* __restrict__ out, int Etot)
{
    extern __shared__ char sm[];
    char* srcb   = sm;                                      // fp16 src tile, 160KB
    int2* se     = (int2*)(sm + SRC_BYTES);                 // [Etot] packed edges, 8B
    int2* s_info = (int2*)(sm + SRC_BYTES + ((Etot * 8 + 15) & ~15));
    float* buf   = (float*)sm;                              // ALIASES src after compute

    const int tid = threadIdx.x, wid = tid >> 5, lane = tid & 31;
    const int lane8 = lane << 3;
    const int b0t = blockIdx.x * TB;

    // ---- stage edges + info into SMEM ----
    for (int i = tid; i < Etot; i += NTHREADS) se[i] = g_edges[i];
    if (tid < NNODES) s_info[tid] = g_info[tid];

    // ---- stage x tile: warp wid owns batch rows 4wid..4wid+3 ----
    {
        const size_t bb = (size_t)(b0t + wid * 4) * IN_DIM;
        #pragma unroll 4
        for (int k = 0; k < 16; ++k) {
            const int c = k * 32 + lane;
            const float v0 = x[bb + c];
            const float v1 = x[bb + IN_DIM + c];
            const float v2 = x[bb + 2 * IN_DIM + c];
            const float v3 = x[bb + 3 * IN_DIM + c];
            const __half2 ha = __floats2half2_rn(v0, v1);
            const __half2 hb = __floats2half2_rn(v2, v3);
            uint2 pv;
            pv.x = h22b(ha);
            pv.y = h22b(hb);
            *(uint2*)(srcb + c * 256 + ((wid ^ lane) << 3)) = pv;  // (c&31)==lane
        }
    }
    __syncthreads();

    // ---- hidden phase: 4 rounds, warp = node (global LPT) ----
    #pragma unroll 1
    for (int rr = 0; rr < NH / NWARPS; ++rr) {
        const int2 I = s_info[rr * NWARPS + wid];
        UNPACK_INFO(I)
        const float4 a = node_accum(srcb, se, lane8, e0, e1, e2, e3, e4);
        uint2 pv;
        pv.x = h22b(__floats2half2_rn(a.x, a.y));
        pv.y = h22b(__floats2half2_rn(a.z, a.w));
        const int hc = IN_DIM + node;
        const int qh = (hc << 8) | ((hc & 31) << 3);
        *(uint2*)(srcb + (qh ^ lane8)) = pv;
    }
    __syncthreads();

    // ---- output phase: all 8 nodes per warp into registers (src stays live) ----
    float4 res[NO / NWARPS];
    #pragma unroll
    for (int rr = 0; rr < NO / NWARPS; ++rr) {
        const int2 I = s_info[NH + rr * NWARPS + wid];
        UNPACK_INFO(I)
        (void)node;
        const float4 a = node_accum(srcb, se, lane8, e0, e1, e2, e3, e4);
        res[rr] = make_float4(tanha(a.x), tanha(a.y), tanha(a.z), tanha(a.w));
    }

    // ---- scatter into transpose buffer (aliases the now-dead src tile) ----
    __syncthreads();
    #pragma unroll
    for (int rr = 0; rr < NO / NWARPS; ++rr) {
        const int node = s_info[NH + rr * NWARPS + wid].y >> 16;
        *(float4*)(buf + node * BUFSTRIDE + lane * 4) = res[rr];
    }
    __syncthreads();

    // ---- coalesced write-out: warp wid handles batch rows 4wid..4wid+3 ----
    #pragma unroll
    for (int j = 0; j < 4; ++j) {
        const int b = wid * 4 + j;
        #pragma unroll
        for (int ch = 0; ch < NO / 32; ++ch) {
            const int cc = ch * 32 + lane;
            out[(size_t)(b0t + b) * NO + cc] = buf[cc * BUFSTRIDE + b];
        }
    }
}

extern "C" void kernel_launch(void* const* d_in, const int* in_sizes, int n_in,
                              void* d_out, int out_size)
{
    const float* x      = (const float*)d_in[0];
    const float* wh     = (const float*)d_in[1];
    const float* wo     = (const float*)d_in[2];
    const int*   rows_h = (const int*)d_in[3];
    const int*   cols_h = (const int*)d_in[4];
    const int*   acts_h = (const int*)d_in[5];
    const int*   rows_o = (const int*)d_in[6];
    const int*   cols_o = (const int*)d_in[7];
    const int*   acts_o = (const int*)d_in[8];
    float* out = (float*)d_out;

    const int Eh = in_sizes[1];
    const int Eo = in_sizes[2];
    const int Etot = Eh + Eo;

    prep_all<<<1, 1024>>>(rows_h, cols_h, acts_h, wh,
                          rows_o, cols_o, acts_o, wo, Eh, Eo);

    const size_t smem = (size_t)SRC_BYTES                   // fp16 src tile (buf aliases)
                      + (size_t)((Etot * 8 + 15) & ~15)     // packed 8B edges
                      + (size_t)NNODES * 8;                 // packed node info
    cudaFuncSetAttribute(wann_main, cudaFuncAttributeMaxDynamicSharedMemorySize,
                         (int)smem);
    wann_main<<<BATCH / TB, NTHREADS, smem>>>(x, out, Etot);
}

// round 12
// speedup vs baseline: 3.1881x; 1.0007x over previous
#include <cuda_runtime.h>
#include <cuda_fp16.h>
#include <cstdint>

#define BATCH    16384
#define IN_DIM   512
#define NH       128
#define NO       256
#define NNODES   (NH + NO)         // 384
#define SRCW     (IN_DIM + NH)     // 640
#define TB       128               // batch rows per tile (4 per lane, fp16)
#define NTHREADS 1024
#define NWARPS   32
#define MAXE     16384
#define SRC_BYTES (SRCW * 256)     // 163840

// src: col-major fp16, 256B/col. (col,b) at byte col*256 + (((b>>2)^(col&31))<<3) + (b&3)*2.
// Lane l reads 8B (batches 4l..4l+3) at q ^ (l<<3), q = col*256 | ((col&31)<<3) [precomputed].
// Edge record (8B): {q, wbits}. identity: wbits = fp32 w.
//                   tanh/relu/sigmoid: wbits = half2(w, w) (sigmoid pre-halved).
// Node info (int2): w0 = e0 | d1<<13 | d2<<21 ; w1 = d3 | d4<<8 | local<<16

__device__ int2 g_edges[MAXE];
__device__ int2 g_info[NNODES];

__device__ __forceinline__ float tanha(float z) {
    float r;
    asm("tanh.approx.f32 %0, %1;" : "=f"(r) : "f"(z));
    return r;
}
__device__ __forceinline__ unsigned tanh_h2(unsigned z) {
    unsigned r;
    asm("tanh.approx.f16x2 %0, %1;" : "=r"(r) : "r"(z));
    return r;
}
__device__ __forceinline__ __half2 b2h2(unsigned b) { __half2 h; *(unsigned*)&h = b; return h; }
__device__ __forceinline__ unsigned h22b(__half2 h) { return *(unsigned*)&h; }

// ================= Fused prep: histogram + scan + scatter + LPT (1 block) =========
__global__ void __launch_bounds__(1024)
prep_all(const int* __restrict__ rows_h, const int* __restrict__ cols_h,
         const int* __restrict__ acts_h, const float* __restrict__ wh,
         const int* __restrict__ rows_o, const int* __restrict__ cols_o,
         const int* __restrict__ acts_o, const float* __restrict__ wo,
         int Eh, int Eo)
{
    __shared__ int cnt[NNODES * 4];
    __shared__ int off[NNODES * 4 + 1];
    __shared__ int wsum[32];

    const int tid = threadIdx.x, lane = tid & 31, wid = tid >> 5;

    for (int i = tid; i < NNODES * 4; i += 1024) cnt[i] = 0;
    __syncthreads();

    for (int e = tid; e < Eh; e += 1024)
        atomicAdd(&cnt[rows_h[e] * 4 + acts_h[e] - 1], 1);
    for (int e = tid; e < Eo; e += 1024)
        atomicAdd(&cnt[(NH + rows_o[e]) * 4 + acts_o[e] - 1], 1);
    __syncthreads();

    if (lane == 0) {
        const int base = wid * 48;
        int run = 0;
        for (int i = 0; i < 48; ++i) { off[base + i] = run; run += cnt[base + i]; }
        wsum[wid] = run;
    }
    __syncthreads();
    if (wid == 0) {
        const int v = wsum[lane];
        int ex = v;
        #pragma unroll
        for (int d = 1; d < 32; d <<= 1) {
            const int t = __shfl_up_sync(0xffffffffu, ex, d);
            if (lane >= d) ex += t;
        }
        ex -= v;
        wsum[lane] = ex;
        if (lane == 31) off[NNODES * 4] = ex + v;
    }
    __syncthreads();
    for (int i = tid; i < NNODES * 4; i += 1024) off[i] += wsum[i / 48];
    __syncthreads();

    // stable scatter: warp per node, ballot compaction per act
    for (int n = wid; n < NNODES; n += 32) {
        const bool hid = n < NH;
        const int* cols = hid ? cols_h : cols_o;
        const int* acts = hid ? acts_h : acts_o;
        const float* wp = hid ? wh : wo;
        const int sub = hid ? 0 : Eh;
        const int s = off[n * 4] - sub;
        const int e = off[(n + 1) * 4] - sub;
        int d0 = off[n * 4], d1 = off[n * 4 + 1], d2 = off[n * 4 + 2], d3 = off[n * 4 + 3];
        for (int c = s; c < e; c += 32) {
            const int idx = c + lane;
            const bool v = idx < e;
            const int act = v ? acts[idx] : 0;
            const int col = v ? cols[idx] : 0;
            const float w = v ? wp[idx] : 0.f;
            const int pk = col * 256 | ((col & 31) << 3);     // precomputed addr word
            #pragma unroll
            for (int a = 1; a <= 4; ++a) {
                const unsigned mm = __ballot_sync(0xffffffffu, act == a);
                int& d = (a == 1) ? d0 : (a == 2) ? d1 : (a == 3) ? d2 : d3;
                if (act == a) {
                    const int r = __popc(mm & ((1u << lane) - 1));
                    int wbits;
                    if (a == 1) {
                        wbits = __float_as_int(w);            // identity: fp32 w
                    } else {                                  // tanh/relu/sigmoid: half2 w
                        const float ww = (a == 4) ? 0.5f * w : w;
                        const __half2 hh = __float2half2_rn(ww);
                        wbits = *(const int*)&hh;
                    }
                    g_edges[d + r] = make_int2(pk, wbits);
                }
                d += __popc(mm);
            }
        }
    }
    __syncthreads();

    // LPT serpentine schedules: hidden over 128, output over all 256. Packed info.
    if (tid < NNODES) {
        const int n = tid;
        const int e0 = off[n * 4], e1 = off[n * 4 + 1], e2 = off[n * 4 + 2];
        const int e3 = off[n * 4 + 3], e4 = off[(n + 1) * 4];
        const int cn = e4 - e0;
        int slot, local;
        if (n < NH) {
            int rank = 0;
            for (int j = 0; j < NH; ++j) {
                const int cj = off[(j + 1) * 4] - off[j * 4];
                rank += (cj > cn) || (cj == cn && j < n);
            }
            const int r = rank >> 5;
            int wl = rank & 31;
            if (r & 1) wl = 31 - wl;
            slot = r * 32 + wl;
            local = n;
        } else {
            int rank = 0;
            for (int j = NH; j < NNODES; ++j) {
                const int cj = off[(j + 1) * 4] - off[j * 4];
                rank += (cj > cn) || (cj == cn && j < n);
            }
            const int r = rank >> 5;
            int wl = rank & 31;
            if (r & 1) wl = 31 - wl;
            slot = NH + r * 32 + wl;
            local = n - NH;
        }
        const int w0 = e0 | ((e1 - e0) << 13) | ((e2 - e1) << 21);
        const int w1 = (e3 - e2) | ((e4 - e3) << 8) | (local << 16);
        g_info[slot] = make_int2(w0, w1);
    }
}

// ================= Main kernel ====================================================
__device__ __forceinline__ float4 node_accum(const char* __restrict__ srcb,
                                             const int2* __restrict__ se,
                                             int lane8,
                                             int e0, int e1, int e2, int e3, int e4)
{
    const float bias = 0.5f * (float)(e4 - e3);
    float a0 = bias, a1 = bias, a2 = bias, a3 = bias;

    // identity: fp32 w, scalar FFMA
    #pragma unroll 4
    for (int e = e0; e < e1; ++e) {
        const int2 ed = se[e];
        const uint2 u = *(const uint2*)(srcb + (ed.x ^ lane8));
        const float w = __int_as_float(ed.y);
        const float2 f0 = __half22float2(b2h2(u.x));
        const float2 f1 = __half22float2(b2h2(u.y));
        a0 = fmaf(w, f0.x, a0); a1 = fmaf(w, f0.y, a1);
        a2 = fmaf(w, f1.x, a2); a3 = fmaf(w, f1.y, a3);
    }
    // tanh: half2 w, HMUL2 + tanh.approx.f16x2, convert, FADD
    #pragma unroll 4
    for (int e = e1; e < e2; ++e) {
        const int2 ed = se[e];
        const uint2 u = *(const uint2*)(srcb + (ed.x ^ lane8));
        const __half2 wh = b2h2((unsigned)ed.y);
        const float2 f0 = __half22float2(b2h2(tanh_h2(h22b(__hmul2(wh, b2h2(u.x))))));
        const float2 f1 = __half22float2(b2h2(tanh_h2(h22b(__hmul2(wh, b2h2(u.y))))));
        a0 += f0.x; a1 += f0.y; a2 += f1.x; a3 += f1.y;
    }
    // relu: half2 w, HMUL2 + HMAX2(0), convert, FADD
    {
        const __half2 z2 = __float2half2_rn(0.f);
        #pragma unroll 4
        for (int e = e2; e < e3; ++e) {
            const int2 ed = se[e];
            const uint2 u = *(const uint2*)(srcb + (ed.x ^ lane8));
            const __half2 wh = b2h2((unsigned)ed.y);
            const float2 f0 = __half22float2(__hmax2(__hmul2(wh, b2h2(u.x)), z2));
            const float2 f1 = __half22float2(__hmax2(__hmul2(wh, b2h2(u.y)), z2));
            a0 += f0.x; a1 += f0.y; a2 += f1.x; a3 += f1.y;
        }
    }
    // sigmoid: half2 w pre-halved; 0.5*tanh (+0.5/edge folded into bias)
    #pragma unroll 4
    for (int e = e3; e < e4; ++e) {
        const int2 ed = se[e];
        const uint2 u = *(const uint2*)(srcb + (ed.x ^ lane8));
        const __half2 wh = b2h2((unsigned)ed.y);
        const float2 f0 = __half22float2(b2h2(tanh_h2(h22b(__hmul2(wh, b2h2(u.x))))));
        const float2 f1 = __half22float2(b2h2(tanh_h2(h22b(__hmul2(wh, b2h2(u.y))))));
        a0 = fmaf(0.5f, f0.x, a0); a1 = fmaf(0.5f, f0.y, a1);
        a2 = fmaf(0.5f, f1.x, a2); a3 = fmaf(0.5f, f1.y, a3);
    }
    return make_float4(a0, a1, a2, a3);
}

#define UNPACK_INFO(I)                                                       \
    const int e0 = (I).x & 8191;                                             \
    const int e1 = e0 + (((I).x >> 13) & 255);                               \
    const int e2 = e1 + (((I).x >> 21) & 255);                               \
    const int e3 = e2 + ((I).y & 255);                                       \
    const int e4 = e3 + (((I).y >> 8) & 255);                                \
    const int node = (I).y >> 16;

__global__ void __launch_bounds__(NTHREADS, 1)
wann_main(const float* __restrict__ x, float* __restrict__ out, int Etot)
{
    extern __shared__ char sm[];
    char* srcb   = sm;                                      // fp16 src tile, 160KB
    int2* se     = (int2*)(sm + SRC_BYTES);                 // [Etot] packed edges, 8B
    int2* s_info = (int2*)(sm + SRC_BYTES + ((Etot * 8 + 15) & ~15));
    // Output buffers alias the (dead-by-then) src tile: two uint arrays,
    // stride 33 words per node row -> conflict-free STS/LDS.
    unsigned* buf1 = (unsigned*)sm;                         // half2(b0,b1) per lane
    unsigned* buf2 = (unsigned*)(sm + NO * 33 * 4);         // half2(b2,b3) per lane

    const int tid = threadIdx.x, wid = tid >> 5, lane = tid & 31;
    const int lane8 = lane << 3;
    const int b0t = blockIdx.x * TB;

    // ---- stage edges + info into SMEM ----
    for (int i = tid; i < Etot; i += NTHREADS) se[i] = g_edges[i];
    if (tid < NNODES) s_info[tid] = g_info[tid];

    // ---- stage x tile: warp wid owns batch rows 4wid..4wid+3 ----
    {
        const size_t bb = (size_t)(b0t + wid * 4) * IN_DIM;
        #pragma unroll 4
        for (int k = 0; k < 16; ++k) {
            const int c = k * 32 + lane;
            const float v0 = x[bb + c];
            const float v1 = x[bb + IN_DIM + c];
            const float v2 = x[bb + 2 * IN_DIM + c];
            const float v3 = x[bb + 3 * IN_DIM + c];
            uint2 pv;
            pv.x = h22b(__floats2half2_rn(v0, v1));
            pv.y = h22b(__floats2half2_rn(v2, v3));
            *(uint2*)(srcb + c * 256 + ((wid ^ lane) << 3)) = pv;  // (c&31)==lane
        }
    }
    __syncthreads();

    // ---- hidden phase: 4 rounds, warp = node (global LPT) ----
    #pragma unroll 1
    for (int rr = 0; rr < NH / NWARPS; ++rr) {
        const int2 I = s_info[rr * NWARPS + wid];
        UNPACK_INFO(I)
        const float4 a = node_accum(srcb, se, lane8, e0, e1, e2, e3, e4);
        uint2 pv;
        pv.x = h22b(__floats2half2_rn(a.x, a.y));
        pv.y = h22b(__floats2half2_rn(a.z, a.w));
        const int hc = IN_DIM + node;
        const int qh = (hc << 8) | ((hc & 31) << 3);
        *(uint2*)(srcb + (qh ^ lane8)) = pv;
    }
    __syncthreads();

    // ---- output phase: 8 nodes per warp; results as half2 pairs (16 regs) ----
    uint2 res[NO / NWARPS];
    #pragma unroll
    for (int rr = 0; rr < NO / NWARPS; ++rr) {
        const int2 I = s_info[NH + rr * NWARPS + wid];
        UNPACK_INFO(I)
        (void)node;
        const float4 a = node_accum(srcb, se, lane8, e0, e1, e2, e3, e4);
        res[rr].x = h22b(__floats2half2_rn(tanha(a.x), tanha(a.y)));
        res[rr].y = h22b(__floats2half2_rn(tanha(a.z), tanha(a.w)));
    }

    // ---- scatter into transpose buffers (alias the now-dead src tile) ----
    __syncthreads();
    #pragma unroll
    for (int rr = 0; rr < NO / NWARPS; ++rr) {
        const int node = s_info[NH + rr * NWARPS + wid].y >> 16;
        buf1[node * 33 + lane] = res[rr].x;
        buf2[node * 33 + lane] = res[rr].y;
    }
    __syncthreads();

    // ---- coalesced write-out: warp wid handles batch rows 4wid..4wid+3 ----
    #pragma unroll
    for (int j = 0; j < 4; ++j) {
        const int b = wid * 4 + j;                      // j selects half2 + element
        const unsigned* bp = (j & 2) ? buf2 : buf1;
        #pragma unroll
        for (int ch = 0; ch < NO / 32; ++ch) {
            const int cc = ch * 32 + lane;
            const __half2 hv = b2h2(bp[cc * 33 + wid]);
            const float f = (j & 1) ? __high2float(hv) : __low2float(hv);
            out[(size_t)(b0t + b) * NO + cc] = f;
        }
    }
}

extern "C" void kernel_launch(void* const* d_in, const int* in_sizes, int n_in,
                              void* d_out, int out_size)
{
    const float* x      = (const float*)d_in[0];
    const float* wh     = (const float*)d_in[1];
    const float* wo     = (const float*)d_in[2];
    const int*   rows_h = (const int*)d_in[3];
    const int*   cols_h = (const int*)d_in[4];
    const int*   acts_h = (const int*)d_in[5];
    const int*   rows_o = (const int*)d_in[6];
    const int*   cols_o = (const int*)d_in[7];
    const int*   acts_o = (const int*)d_in[8];
    float* out = (float*)d_out;

    const int Eh = in_sizes[1];
    const int Eo = in_sizes[2];
    const int Etot = Eh + Eo;

    prep_all<<<1, 1024>>>(rows_h, cols_h, acts_h, wh,
                          rows_o, cols_o, acts_o, wo, Eh, Eo);

    const size_t smem = (size_t)SRC_BYTES                   // fp16 src tile (bufs alias)
                      + (size_t)((Etot * 8 + 15) & ~15)     // packed 8B edges
                      + (size_t)NNODES * 8;                 // packed node info
    cudaFuncSetAttribute(wann_main, cudaFuncAttributeMaxDynamicSharedMemorySize,
                         (int)smem);
    wann_main<<<BATCH / TB, NTHREADS, smem>>>(x, out, Etot);
}